// round 15
// baseline (speedup 1.0000x reference)
#include <cuda_runtime.h>
#include <cuda_bf16.h>
#include <cstdint>

// Sinkhorn OT, B=1024, N=M=256, <=100 iters. One CTA (512 threads) per batch
// (static grid, R12 base). bf16 HMMA + exact-fixed-point early exit, plus:
//  - geometric Aitken extrapolation u <- u^2/u_prev at iterations 2 and 5
//    (scale-safe: Sinkhorn map is 1-homogeneous, P is scale-invariant, exit
//    only fires at a genuine bf16 fixed point, positivity preserved)
//  - final mean folded into the kernel via threadfence-reduction (1 launch).
// Warp w fully owns K-cols 16w..+15 (matvec1, A-frags of K^T in registers)
// and K-rows 16w..+15 (matvec2, A = conflict-free smem words). 2 barriers/iter.

#define B_TOT   1024
#define ITERS   100
#define INV_EPS 10.0f
#define EPS_DIV 1e-8f

#define ROWW_W  132                        // words per padded K row
#define KROW_H  264                        // bf16 per padded K row
#define OFF_A   (256*ROWW_W*4)             // 135168
#define OFF_B   (OFF_A + 1024)
#define OFF_U   (OFF_B + 1024)
#define OFF_V   (OFF_U + 1024)
#define OFF_UP  (OFF_V + 1024)             // uperm: 160 words (640B)
#define OFF_VP  (OFF_UP + 640)             // vperm: 160 words
#define OFF_PS  (OFF_VP + 640)             // 576 floats scratch (+chg flags)
#define SMEM_BYTES (OFF_PS + 2304)         // 142848

__device__ float g_cost[B_TOT];
__device__ unsigned int g_done;            // zero-init; last CTA self-resets

__device__ __forceinline__ float bflo(unsigned int p) { return __uint_as_float(p << 16); }
__device__ __forceinline__ float bfhi(unsigned int p) { return __uint_as_float(p & 0xffff0000u); }

__device__ __forceinline__ void mma16816(float& d0, float& d1, float& d2, float& d3,
                                         uint32_t a0, uint32_t a1, uint32_t a2, uint32_t a3,
                                         uint32_t b0, uint32_t b1) {
    asm volatile("mma.sync.aligned.m16n8k16.row.col.f32.bf16.bf16.f32 "
                 "{%0,%1,%2,%3}, {%4,%5,%6,%7}, {%8,%9}, {%0,%1,%2,%3};"
                 : "+f"(d0), "+f"(d1), "+f"(d2), "+f"(d3)
                 : "r"(a0), "r"(a1), "r"(a2), "r"(a3), "r"(b0), "r"(b1));
}

// pack K[r][c], K[r+1][c] (bf16 bits) into one b32 (lo = row r)
__device__ __forceinline__ uint32_t ld2k(const unsigned short* sK, int r, int c) {
    uint32_t lo = sK[r * KROW_H + c];
    uint32_t hi = sK[(r + 1) * KROW_H + c];
    return lo | (hi << 16);
}

// Publish x0 (=vec[16w+lq]) / x1 (=vec[16w+lq+8]) into the permuted 4-copy
// bf16 layout: perm[36c + 2w + h] = {vec[16w+2c+8h], vec[16w+2c+8h+1]}.
__device__ __forceinline__ void publish_perm(uint32_t* perm, int w, int lane,
                                             float x0, float x1) {
    int c = (lane >> 1) & 3;
    int h = lane & 1;
    float s00 = __shfl_sync(0xffffffffu, x0, 8*c);
    float s01 = __shfl_sync(0xffffffffu, x0, 8*c + 4);
    float s10 = __shfl_sync(0xffffffffu, x1, 8*c);
    float s11 = __shfl_sync(0xffffffffu, x1, 8*c + 4);
    float lo = h ? s10 : s00;
    float hi = h ? s11 : s01;
    __nv_bfloat162 p = __floats2bfloat162_rn(lo, hi);
    if (lane < 8) perm[36*c + 2*w + h] = *(uint32_t*)&p;
}

extern __shared__ unsigned char smem_raw[];

__global__ __launch_bounds__(512, 1)
void sinkhorn_kernel(const float* __restrict__ C,
                     const float* __restrict__ mass_pred,
                     const float* __restrict__ mass_target,
                     float* __restrict__ out)
{
    unsigned short* sK = (unsigned short*)smem_raw;            // 256 x 264 bf16
    const unsigned int* sKw = (const unsigned int*)smem_raw;   // word view
    float* s_a  = (float*)(smem_raw + OFF_A);
    float* s_b  = (float*)(smem_raw + OFF_B);
    float* s_u  = (float*)(smem_raw + OFF_U);
    float* s_v  = (float*)(smem_raw + OFF_V);
    uint32_t* uperm = (uint32_t*)(smem_raw + OFF_UP);
    uint32_t* vperm = (uint32_t*)(smem_raw + OFF_VP);
    const uint4* up4 = (const uint4*)(smem_raw + OFF_UP);
    const uint4* vp4 = (const uint4*)(smem_raw + OFF_VP);
    float* s_ps = (float*)(smem_raw + OFF_PS);
    int*   s_chg = (int*)(smem_raw + OFF_PS);     // reused during iterations

    const int b    = blockIdx.x;
    const int t    = threadIdx.x;
    const int w    = t >> 5;        // warp 0..15
    const int lane = t & 31;
    const int lq   = lane >> 2;     // 0..7
    const int lr   = lane & 3;      // 0..3
    const float* __restrict__ Cb = C + (size_t)b * 65536;

    // ---------- Build K = exp(-C/eps) (bf16, padded rows) ----------
    #pragma unroll 4
    for (int k = 0; k < 32; k++) {
        int idx4 = k * 512 + t;
        float4 c = ((const float4*)Cb)[idx4];
        int lin = idx4 << 2;
        int n = lin >> 8;
        int m = lin & 255;
        __nv_bfloat162 p0 = __floats2bfloat162_rn(__expf(-c.x * INV_EPS),
                                                  __expf(-c.y * INV_EPS));
        __nv_bfloat162 p1 = __floats2bfloat162_rn(__expf(-c.z * INV_EPS),
                                                  __expf(-c.w * INV_EPS));
        *(__nv_bfloat162*)&sK[n * KROW_H + m]     = p0;
        *(__nv_bfloat162*)&sK[n * KROW_H + m + 2] = p1;
    }

    // ---------- Normalize masses (threads 0-255), s_ps scratch ----------
    if (t < 256) {
        float mpv = mass_pred[b * 256 + t];
        float mtv = mass_target[b * 256 + t];
        float sa = mpv, sb = mtv;
        #pragma unroll
        for (int o = 16; o; o >>= 1) {
            sa += __shfl_xor_sync(0xffffffffu, sa, o);
            sb += __shfl_xor_sync(0xffffffffu, sb, o);
        }
        if ((t & 31) == 0) { s_ps[t >> 5] = sa; s_ps[8 + (t >> 5)] = sb; }
        s_ps[64 + t]  = mpv;
        s_ps[320 + t] = mtv;
    }
    // init uperm = all 1.0 bf16 pairs
    if (t < 160) uperm[t] = 0x3F803F80u;
    __syncthreads();
    if (t < 256) {
        float suma = 0.f, sumb = 0.f;
        #pragma unroll
        for (int q = 0; q < 8; q++) { suma += s_ps[q]; sumb += s_ps[8 + q]; }
        s_a[t] = s_ps[64 + t]  / (suma + EPS_DIV);
        s_b[t] = s_ps[320 + t] / (sumb + EPS_DIV);
        s_u[t] = 1.0f;
    }
    __syncthreads();

    // ---------- Persistent A-frags of K^T: warp's 16 cols x all 256 rows ----------
    uint32_t af[16][4];
    #pragma unroll
    for (int kt = 0; kt < 16; kt++) {
        int r = 16*kt + 2*lr;
        int c = 16*w + lq;
        af[kt][0] = ld2k(sK, r,     c);
        af[kt][1] = ld2k(sK, r,     c + 8);
        af[kt][2] = ld2k(sK, r + 8, c);
        af[kt][3] = ld2k(sK, r + 8, c + 8);
    }

    // Hoisted per-thread constants
    const float sa0 = s_a[16*w + lq];
    const float sa1 = s_a[16*w + lq + 8];
    const float sb0 = s_b[16*w + lq];
    const float sb1 = s_b[16*w + lq + 8];
    const int rA = (16*w + lq)     * ROWW_W;
    const int rB = (16*w + lq + 8) * ROWW_W;

    uint32_t pu = 0u;        // previous bf16x2 image of (u0,u1)
    float pu0 = 1.0f, pu1 = 1.0f;   // previous fp32 u (for extrapolation)

    // ---------- Sinkhorn iterations: Aitken accel + exact-fixed-point exit ----------
    for (int it = 0; it < ITERS; it++) {
        // ===== matvec1: Kt_u for cols 16w..+15 (af as A, u-perm as B) =====
        {
            float d0[4] = {0,0,0,0}, d1[4] = {0,0,0,0};
            float d2[4] = {0,0,0,0}, d3[4] = {0,0,0,0};
            #pragma unroll
            for (int s = 0; s < 8; s++) {
                uint4 bb = up4[9*lr + s];          // (b0,b1) for kt=2s and 2s+1
                int k0 = 2*s, k1 = 2*s + 1;
                int s0 = k0 & 3, s1 = k1 & 3;
                mma16816(d0[s0], d1[s0], d2[s0], d3[s0],
                         af[k0][0], af[k0][1], af[k0][2], af[k0][3], bb.x, bb.y);
                mma16816(d0[s1], d1[s1], d2[s1], d3[s1],
                         af[k1][0], af[k1][1], af[k1][2], af[k1][3], bb.z, bb.w);
            }
            float ktu0 = (d0[0] + d0[1]) + (d0[2] + d0[3]);
            float ktu1 = (d2[0] + d2[1]) + (d2[2] + d2[3]);
            float v0 = __fdividef(sb0, ktu0 + EPS_DIV);
            float v1 = __fdividef(sb1, ktu1 + EPS_DIV);
            if (lr == 0) { s_v[16*w + lq] = v0; s_v[16*w + lq + 8] = v1; }
            publish_perm(vperm, w, lane, v0, v1);
        }
        __syncthreads();

        // ===== matvec2: K_v for rows 16w..+15 (smem K as A, v-perm as B) =====
        {
            float d0[4] = {0,0,0,0}, d1[4] = {0,0,0,0};
            float d2[4] = {0,0,0,0}, d3[4] = {0,0,0,0};
            #pragma unroll
            for (int s = 0; s < 8; s++) {
                uint4 bb = vp4[9*lr + s];
                #pragma unroll
                for (int q = 0; q < 2; q++) {
                    int kt = 2*s + q;
                    int ss = kt & 3;
                    uint32_t a0 = sKw[rA + 8*kt + lr];
                    uint32_t a1 = sKw[rB + 8*kt + lr];
                    uint32_t a2 = sKw[rA + 8*kt + lr + 4];
                    uint32_t a3 = sKw[rB + 8*kt + lr + 4];
                    mma16816(d0[ss], d1[ss], d2[ss], d3[ss],
                             a0, a1, a2, a3,
                             q ? bb.z : bb.x, q ? bb.w : bb.y);
                }
            }
            float kv0 = (d0[0] + d0[1]) + (d0[2] + d0[3]);
            float kv1 = (d2[0] + d2[1]) + (d2[2] + d2[3]);
            float u0 = __fdividef(sa0, kv0 + EPS_DIV);
            float u1 = __fdividef(sa1, kv1 + EPS_DIV);

            // -- geometric Aitken extrapolation (scale-safe, positive) --
            if (it == 2 || it == 5) {
                u0 = __fdividef(u0 * u0, pu0);
                u1 = __fdividef(u1 * u1, pu1);
            }
            pu0 = u0;  pu1 = u1;

            if (lr == 0) { s_u[16*w + lq] = u0; s_u[16*w + lq + 8] = u1; }
            publish_perm(uperm, w, lane, u0, u1);

            // -- convergence flag: has the bf16 image of u changed? --
            __nv_bfloat162 upk = __floats2bfloat162_rn(u0, u1);
            uint32_t uw = *(uint32_t*)&upk;
            int ch = __any_sync(0xffffffffu, uw != pu);
            pu = uw;
            if (lane == 0) s_chg[w] = ch;
        }
        __syncthreads();

        // CTA-uniform exit (bf16 image stable => all later iters no-op)
        {
            int4 c0 = *(const int4*)&s_chg[0];
            int4 c1 = *(const int4*)&s_chg[4];
            int4 c2 = *(const int4*)&s_chg[8];
            int4 c3 = *(const int4*)&s_chg[12];
            int any = (c0.x | c0.y | c0.z | c0.w) | (c1.x | c1.y | c1.z | c1.w)
                    | (c2.x | c2.y | c2.z | c2.w) | (c3.x | c3.y | c3.z | c3.w);
            if (!any) break;
        }
    }
    __syncthreads();

    // ---------- ot_cost[b] = sum u[n] K[n,m] v[m] C[n,m] (C from L2) ----------
    float accf = 0.f;
    #pragma unroll 4
    for (int k = 0; k < 32; k++) {
        int idx4 = k * 512 + t;
        float4 c = ((const float4*)Cb)[idx4];
        int lin = idx4 << 2;
        int n = lin >> 8;
        int m = lin & 255;
        uint2 q = *(const uint2*)&sKw[n * ROWW_W + (m >> 1)];
        float un = s_u[n];
        float4 vv = *(const float4*)&s_v[m];
        accf += un * (bflo(q.x) * vv.x * c.x + bfhi(q.x) * vv.y * c.y
                    + bflo(q.y) * vv.z * c.z + bfhi(q.y) * vv.w * c.w);
    }
    #pragma unroll
    for (int o = 16; o; o >>= 1) accf += __shfl_xor_sync(0xffffffffu, accf, o);
    __syncthreads();
    if ((t & 31) == 0) s_ps[t >> 5] = accf;
    __syncthreads();

    __shared__ int s_last;
    if (t == 0) {
        float s = 0.f;
        #pragma unroll
        for (int q = 0; q < 16; q++) s += s_ps[q];
        g_cost[b] = s;
        __threadfence();
        unsigned int done = atomicAdd(&g_done, 1u);
        s_last = (done == B_TOT - 1);
    }
    __syncthreads();

    // ---------- Last CTA: deterministic fixed-tree mean over g_cost ----------
    if (s_last) {
        __threadfence();                 // acquire: all g_cost writes visible
        float s = g_cost[t] + g_cost[t + 512];
        #pragma unroll
        for (int o = 16; o; o >>= 1) s += __shfl_xor_sync(0xffffffffu, s, o);
        if (lane == 0) s_ps[w] = s;
        __syncthreads();
        if (t == 0) {
            float tot = 0.f;
            #pragma unroll
            for (int q = 0; q < 16; q++) tot += s_ps[q];
            out[0] = tot * (1.0f / B_TOT);
            g_done = 0;                  // self-reset for graph replay
        }
    }
}

extern "C" void kernel_launch(void* const* d_in, const int* in_sizes, int n_in,
                              void* d_out, int out_size)
{
    const float* C  = (const float*)d_in[0];
    const float* mp = (const float*)d_in[1];
    const float* mt = (const float*)d_in[2];
    float* out = (float*)d_out;

    cudaFuncSetAttribute(sinkhorn_kernel,
                         cudaFuncAttributeMaxDynamicSharedMemorySize, SMEM_BYTES);

    sinkhorn_kernel<<<B_TOT, 512, SMEM_BYTES>>>(C, mp, mt, out);
}

// round 16
// speedup vs baseline: 1.0584x; 1.0584x over previous
#include <cuda_runtime.h>
#include <cuda_bf16.h>
#include <cstdint>

// Sinkhorn OT, B=1024, N=M=256, <=100 iters. One CTA (512 threads) per batch.
// bf16 HMMA + exact-fixed-point early exit (R12 core) +
//  - u0 = a initialization (fixed point has u ~ a; cuts startup iterations;
//    scale-safe: map is 1-homogeneous, P scale-invariant, exit only at a
//    genuine bf16 fixed point)
//  - final mean fused into the kernel via threadfence-reduction (1 launch).
// Warp w fully owns K-cols 16w..+15 (matvec1, A-frags of K^T in registers)
// and K-rows 16w..+15 (matvec2, A = conflict-free smem words). 2 barriers/iter.

#define B_TOT   1024
#define ITERS   100
#define INV_EPS 10.0f
#define EPS_DIV 1e-8f

#define ROWW_W  132                        // words per padded K row
#define KROW_H  264                        // bf16 per padded K row
#define OFF_A   (256*ROWW_W*4)             // 135168
#define OFF_B   (OFF_A + 1024)
#define OFF_U   (OFF_B + 1024)
#define OFF_V   (OFF_U + 1024)
#define OFF_UP  (OFF_V + 1024)             // uperm: 160 words (640B)
#define OFF_VP  (OFF_UP + 640)             // vperm: 160 words
#define OFF_PS  (OFF_VP + 640)             // 576 floats scratch (+chg flags)
#define SMEM_BYTES (OFF_PS + 2304)         // 142848

__device__ float g_cost[B_TOT];
__device__ unsigned int g_done;            // zero-init; last CTA self-resets

__device__ __forceinline__ float bflo(unsigned int p) { return __uint_as_float(p << 16); }
__device__ __forceinline__ float bfhi(unsigned int p) { return __uint_as_float(p & 0xffff0000u); }

__device__ __forceinline__ void mma16816(float& d0, float& d1, float& d2, float& d3,
                                         uint32_t a0, uint32_t a1, uint32_t a2, uint32_t a3,
                                         uint32_t b0, uint32_t b1) {
    asm volatile("mma.sync.aligned.m16n8k16.row.col.f32.bf16.bf16.f32 "
                 "{%0,%1,%2,%3}, {%4,%5,%6,%7}, {%8,%9}, {%0,%1,%2,%3};"
                 : "+f"(d0), "+f"(d1), "+f"(d2), "+f"(d3)
                 : "r"(a0), "r"(a1), "r"(a2), "r"(a3), "r"(b0), "r"(b1));
}

// pack K[r][c], K[r+1][c] (bf16 bits) into one b32 (lo = row r)
__device__ __forceinline__ uint32_t ld2k(const unsigned short* sK, int r, int c) {
    uint32_t lo = sK[r * KROW_H + c];
    uint32_t hi = sK[(r + 1) * KROW_H + c];
    return lo | (hi << 16);
}

// Publish x0 (=vec[16w+lq]) / x1 (=vec[16w+lq+8]) into the permuted 4-copy
// bf16 layout: perm[36c + 2w + h] = {vec[16w+2c+8h], vec[16w+2c+8h+1]}.
__device__ __forceinline__ void publish_perm(uint32_t* perm, int w, int lane,
                                             float x0, float x1) {
    int c = (lane >> 1) & 3;
    int h = lane & 1;
    float s00 = __shfl_sync(0xffffffffu, x0, 8*c);
    float s01 = __shfl_sync(0xffffffffu, x0, 8*c + 4);
    float s10 = __shfl_sync(0xffffffffu, x1, 8*c);
    float s11 = __shfl_sync(0xffffffffu, x1, 8*c + 4);
    float lo = h ? s10 : s00;
    float hi = h ? s11 : s01;
    __nv_bfloat162 p = __floats2bfloat162_rn(lo, hi);
    if (lane < 8) perm[36*c + 2*w + h] = *(uint32_t*)&p;
}

extern __shared__ unsigned char smem_raw[];

__global__ __launch_bounds__(512, 1)
void sinkhorn_kernel(const float* __restrict__ C,
                     const float* __restrict__ mass_pred,
                     const float* __restrict__ mass_target,
                     float* __restrict__ out)
{
    unsigned short* sK = (unsigned short*)smem_raw;            // 256 x 264 bf16
    const unsigned int* sKw = (const unsigned int*)smem_raw;   // word view
    float* s_a  = (float*)(smem_raw + OFF_A);
    float* s_b  = (float*)(smem_raw + OFF_B);
    float* s_u  = (float*)(smem_raw + OFF_U);
    float* s_v  = (float*)(smem_raw + OFF_V);
    uint32_t* uperm = (uint32_t*)(smem_raw + OFF_UP);
    uint32_t* vperm = (uint32_t*)(smem_raw + OFF_VP);
    const uint4* up4 = (const uint4*)(smem_raw + OFF_UP);
    const uint4* vp4 = (const uint4*)(smem_raw + OFF_VP);
    float* s_ps = (float*)(smem_raw + OFF_PS);
    int*   s_chg = (int*)(smem_raw + OFF_PS);     // reused during iterations

    const int b    = blockIdx.x;
    const int t    = threadIdx.x;
    const int w    = t >> 5;        // warp 0..15
    const int lane = t & 31;
    const int lq   = lane >> 2;     // 0..7
    const int lr   = lane & 3;      // 0..3
    const float* __restrict__ Cb = C + (size_t)b * 65536;

    // ---------- Build K = exp(-C/eps) (bf16, padded rows) ----------
    #pragma unroll 4
    for (int k = 0; k < 32; k++) {
        int idx4 = k * 512 + t;
        float4 c = ((const float4*)Cb)[idx4];
        int lin = idx4 << 2;
        int n = lin >> 8;
        int m = lin & 255;
        __nv_bfloat162 p0 = __floats2bfloat162_rn(__expf(-c.x * INV_EPS),
                                                  __expf(-c.y * INV_EPS));
        __nv_bfloat162 p1 = __floats2bfloat162_rn(__expf(-c.z * INV_EPS),
                                                  __expf(-c.w * INV_EPS));
        *(__nv_bfloat162*)&sK[n * KROW_H + m]     = p0;
        *(__nv_bfloat162*)&sK[n * KROW_H + m + 2] = p1;
    }

    // ---------- Normalize masses (threads 0-255), s_ps scratch ----------
    if (t < 256) {
        float mpv = mass_pred[b * 256 + t];
        float mtv = mass_target[b * 256 + t];
        float sa = mpv, sb = mtv;
        #pragma unroll
        for (int o = 16; o; o >>= 1) {
            sa += __shfl_xor_sync(0xffffffffu, sa, o);
            sb += __shfl_xor_sync(0xffffffffu, sb, o);
        }
        if ((t & 31) == 0) { s_ps[t >> 5] = sa; s_ps[8 + (t >> 5)] = sb; }
        s_ps[64 + t]  = mpv;
        s_ps[320 + t] = mtv;
    }
    __syncthreads();
    if (t < 256) {
        float suma = 0.f, sumb = 0.f;
        #pragma unroll
        for (int q = 0; q < 8; q++) { suma += s_ps[q]; sumb += s_ps[8 + q]; }
        s_a[t] = s_ps[64 + t]  / (suma + EPS_DIV);
        s_b[t] = s_ps[320 + t] / (sumb + EPS_DIV);
    }
    __syncthreads();

    // ---------- Persistent A-frags of K^T: warp's 16 cols x all 256 rows ----------
    uint32_t af[16][4];
    #pragma unroll
    for (int kt = 0; kt < 16; kt++) {
        int r = 16*kt + 2*lr;
        int c = 16*w + lq;
        af[kt][0] = ld2k(sK, r,     c);
        af[kt][1] = ld2k(sK, r,     c + 8);
        af[kt][2] = ld2k(sK, r + 8, c);
        af[kt][3] = ld2k(sK, r + 8, c + 8);
    }

    // Hoisted per-thread constants
    const float sa0 = s_a[16*w + lq];
    const float sa1 = s_a[16*w + lq + 8];
    const float sb0 = s_b[16*w + lq];
    const float sb1 = s_b[16*w + lq + 8];
    const int rA = (16*w + lq)     * ROWW_W;
    const int rB = (16*w + lq + 8) * ROWW_W;

    // ---------- u0 = a (fixed point has u ~ a; scale-safe) ----------
    if (lr == 0) { s_u[16*w + lq] = sa0; s_u[16*w + lq + 8] = sa1; }
    publish_perm(uperm, w, lane, sa0, sa1);
    __syncthreads();

    uint32_t pu = 0u;        // previous bf16x2 image of (u0,u1); 0 != any image

    // ---------- Sinkhorn iterations with exact-fixed-point exit ----------
    for (int it = 0; it < ITERS; it++) {
        // ===== matvec1: Kt_u for cols 16w..+15 (af as A, u-perm as B) =====
        {
            float d0[4] = {0,0,0,0}, d1[4] = {0,0,0,0};
            float d2[4] = {0,0,0,0}, d3[4] = {0,0,0,0};
            #pragma unroll
            for (int s = 0; s < 8; s++) {
                uint4 bb = up4[9*lr + s];          // (b0,b1) for kt=2s and 2s+1
                int k0 = 2*s, k1 = 2*s + 1;
                int s0 = k0 & 3, s1 = k1 & 3;
                mma16816(d0[s0], d1[s0], d2[s0], d3[s0],
                         af[k0][0], af[k0][1], af[k0][2], af[k0][3], bb.x, bb.y);
                mma16816(d0[s1], d1[s1], d2[s1], d3[s1],
                         af[k1][0], af[k1][1], af[k1][2], af[k1][3], bb.z, bb.w);
            }
            float ktu0 = (d0[0] + d0[1]) + (d0[2] + d0[3]);
            float ktu1 = (d2[0] + d2[1]) + (d2[2] + d2[3]);
            float v0 = __fdividef(sb0, ktu0 + EPS_DIV);
            float v1 = __fdividef(sb1, ktu1 + EPS_DIV);
            if (lr == 0) { s_v[16*w + lq] = v0; s_v[16*w + lq + 8] = v1; }
            publish_perm(vperm, w, lane, v0, v1);
        }
        __syncthreads();

        // ===== matvec2: K_v for rows 16w..+15 (smem K as A, v-perm as B) =====
        {
            float d0[4] = {0,0,0,0}, d1[4] = {0,0,0,0};
            float d2[4] = {0,0,0,0}, d3[4] = {0,0,0,0};
            #pragma unroll
            for (int s = 0; s < 8; s++) {
                uint4 bb = vp4[9*lr + s];
                #pragma unroll
                for (int q = 0; q < 2; q++) {
                    int kt = 2*s + q;
                    int ss = kt & 3;
                    uint32_t a0 = sKw[rA + 8*kt + lr];
                    uint32_t a1 = sKw[rB + 8*kt + lr];
                    uint32_t a2 = sKw[rA + 8*kt + lr + 4];
                    uint32_t a3 = sKw[rB + 8*kt + lr + 4];
                    mma16816(d0[ss], d1[ss], d2[ss], d3[ss],
                             a0, a1, a2, a3,
                             q ? bb.z : bb.x, q ? bb.w : bb.y);
                }
            }
            float kv0 = (d0[0] + d0[1]) + (d0[2] + d0[3]);
            float kv1 = (d2[0] + d2[1]) + (d2[2] + d2[3]);
            float u0 = __fdividef(sa0, kv0 + EPS_DIV);
            float u1 = __fdividef(sa1, kv1 + EPS_DIV);
            if (lr == 0) { s_u[16*w + lq] = u0; s_u[16*w + lq + 8] = u1; }
            publish_perm(uperm, w, lane, u0, u1);

            // -- convergence flag: has the bf16 image of u changed? --
            __nv_bfloat162 upk = __floats2bfloat162_rn(u0, u1);
            uint32_t uw = *(uint32_t*)&upk;
            int ch = __any_sync(0xffffffffu, uw != pu);
            pu = uw;
            if (lane == 0) s_chg[w] = ch;
        }
        __syncthreads();

        // CTA-uniform exit (bf16 image stable => all later iters no-op)
        {
            int4 c0 = *(const int4*)&s_chg[0];
            int4 c1 = *(const int4*)&s_chg[4];
            int4 c2 = *(const int4*)&s_chg[8];
            int4 c3 = *(const int4*)&s_chg[12];
            int any = (c0.x | c0.y | c0.z | c0.w) | (c1.x | c1.y | c1.z | c1.w)
                    | (c2.x | c2.y | c2.z | c2.w) | (c3.x | c3.y | c3.z | c3.w);
            if (!any) break;
        }
    }
    __syncthreads();

    // ---------- ot_cost[b] = sum u[n] K[n,m] v[m] C[n,m] (C from L2) ----------
    float accf = 0.f;
    #pragma unroll 4
    for (int k = 0; k < 32; k++) {
        int idx4 = k * 512 + t;
        float4 c = ((const float4*)Cb)[idx4];
        int lin = idx4 << 2;
        int n = lin >> 8;
        int m = lin & 255;
        uint2 q = *(const uint2*)&sKw[n * ROWW_W + (m >> 1)];
        float un = s_u[n];
        float4 vv = *(const float4*)&s_v[m];
        accf += un * (bflo(q.x) * vv.x * c.x + bfhi(q.x) * vv.y * c.y
                    + bflo(q.y) * vv.z * c.z + bfhi(q.y) * vv.w * c.w);
    }
    #pragma unroll
    for (int o = 16; o; o >>= 1) accf += __shfl_xor_sync(0xffffffffu, accf, o);
    __syncthreads();
    if ((t & 31) == 0) s_ps[t >> 5] = accf;
    __syncthreads();

    __shared__ int s_last;
    if (t == 0) {
        float s = 0.f;
        #pragma unroll
        for (int q = 0; q < 16; q++) s += s_ps[q];
        g_cost[b] = s;
        __threadfence();
        unsigned int done = atomicAdd(&g_done, 1u);
        s_last = (done == B_TOT - 1);
    }
    __syncthreads();

    // ---------- Last CTA: deterministic fixed-tree mean over g_cost ----------
    if (s_last) {
        __threadfence();                 // acquire: all g_cost writes visible
        float s = g_cost[t] + g_cost[t + 512];
        #pragma unroll
        for (int o = 16; o; o >>= 1) s += __shfl_xor_sync(0xffffffffu, s, o);
        if (lane == 0) s_ps[w] = s;
        __syncthreads();
        if (t == 0) {
            float tot = 0.f;
            #pragma unroll
            for (int q = 0; q < 16; q++) tot += s_ps[q];
            out[0] = tot * (1.0f / B_TOT);
            g_done = 0;                  // self-reset for graph replay
        }
    }
}

extern "C" void kernel_launch(void* const* d_in, const int* in_sizes, int n_in,
                              void* d_out, int out_size)
{
    const float* C  = (const float*)d_in[0];
    const float* mp = (const float*)d_in[1];
    const float* mt = (const float*)d_in[2];
    float* out = (float*)d_out;

    cudaFuncSetAttribute(sinkhorn_kernel,
                         cudaFuncAttributeMaxDynamicSharedMemorySize, SMEM_BYTES);

    sinkhorn_kernel<<<B_TOT, 512, SMEM_BYTES>>>(C, mp, mt, out);
}

// round 17
// speedup vs baseline: 1.1374x; 1.0746x over previous
#include <cuda_runtime.h>
#include <cuda_bf16.h>
#include <cstdint>

// Sinkhorn OT, B=1024, N=M=256, <=100 iters. One CTA (512 threads) per batch.
// R12 bf16-HMMA core (u0=1, exact-fixed-point early exit) +
//  - final mean fused into the kernel via threadfence-reduction (1 launch)
//  - K-build loop unroll 8 (double LDG MLP; build is DRAM-latency exposed).
// Warp w fully owns K-cols 16w..+15 (matvec1, A-frags of K^T in registers)
// and K-rows 16w..+15 (matvec2, A = conflict-free smem words). 2 barriers/iter.

#define B_TOT   1024
#define ITERS   100
#define INV_EPS 10.0f
#define EPS_DIV 1e-8f

#define ROWW_W  132                        // words per padded K row
#define KROW_H  264                        // bf16 per padded K row
#define OFF_A   (256*ROWW_W*4)             // 135168
#define OFF_B   (OFF_A + 1024)
#define OFF_U   (OFF_B + 1024)
#define OFF_V   (OFF_U + 1024)
#define OFF_UP  (OFF_V + 1024)             // uperm: 160 words (640B)
#define OFF_VP  (OFF_UP + 640)             // vperm: 160 words
#define OFF_PS  (OFF_VP + 640)             // 576 floats scratch (+chg flags)
#define SMEM_BYTES (OFF_PS + 2304)         // 142848

__device__ float g_cost[B_TOT];
__device__ unsigned int g_done;            // zero-init; last CTA self-resets

__device__ __forceinline__ float bflo(unsigned int p) { return __uint_as_float(p << 16); }
__device__ __forceinline__ float bfhi(unsigned int p) { return __uint_as_float(p & 0xffff0000u); }

__device__ __forceinline__ void mma16816(float& d0, float& d1, float& d2, float& d3,
                                         uint32_t a0, uint32_t a1, uint32_t a2, uint32_t a3,
                                         uint32_t b0, uint32_t b1) {
    asm volatile("mma.sync.aligned.m16n8k16.row.col.f32.bf16.bf16.f32 "
                 "{%0,%1,%2,%3}, {%4,%5,%6,%7}, {%8,%9}, {%0,%1,%2,%3};"
                 : "+f"(d0), "+f"(d1), "+f"(d2), "+f"(d3)
                 : "r"(a0), "r"(a1), "r"(a2), "r"(a3), "r"(b0), "r"(b1));
}

// pack K[r][c], K[r+1][c] (bf16 bits) into one b32 (lo = row r)
__device__ __forceinline__ uint32_t ld2k(const unsigned short* sK, int r, int c) {
    uint32_t lo = sK[r * KROW_H + c];
    uint32_t hi = sK[(r + 1) * KROW_H + c];
    return lo | (hi << 16);
}

// Publish x0 (=vec[16w+lq]) / x1 (=vec[16w+lq+8]) into the permuted 4-copy
// bf16 layout: perm[36c + 2w + h] = {vec[16w+2c+8h], vec[16w+2c+8h+1]}.
__device__ __forceinline__ void publish_perm(uint32_t* perm, int w, int lane,
                                             float x0, float x1) {
    int c = (lane >> 1) & 3;
    int h = lane & 1;
    float s00 = __shfl_sync(0xffffffffu, x0, 8*c);
    float s01 = __shfl_sync(0xffffffffu, x0, 8*c + 4);
    float s10 = __shfl_sync(0xffffffffu, x1, 8*c);
    float s11 = __shfl_sync(0xffffffffu, x1, 8*c + 4);
    float lo = h ? s10 : s00;
    float hi = h ? s11 : s01;
    __nv_bfloat162 p = __floats2bfloat162_rn(lo, hi);
    if (lane < 8) perm[36*c + 2*w + h] = *(uint32_t*)&p;
}

extern __shared__ unsigned char smem_raw[];

__global__ __launch_bounds__(512, 1)
void sinkhorn_kernel(const float* __restrict__ C,
                     const float* __restrict__ mass_pred,
                     const float* __restrict__ mass_target,
                     float* __restrict__ out)
{
    unsigned short* sK = (unsigned short*)smem_raw;            // 256 x 264 bf16
    const unsigned int* sKw = (const unsigned int*)smem_raw;   // word view
    float* s_a  = (float*)(smem_raw + OFF_A);
    float* s_b  = (float*)(smem_raw + OFF_B);
    float* s_u  = (float*)(smem_raw + OFF_U);
    float* s_v  = (float*)(smem_raw + OFF_V);
    uint32_t* uperm = (uint32_t*)(smem_raw + OFF_UP);
    uint32_t* vperm = (uint32_t*)(smem_raw + OFF_VP);
    const uint4* up4 = (const uint4*)(smem_raw + OFF_UP);
    const uint4* vp4 = (const uint4*)(smem_raw + OFF_VP);
    float* s_ps = (float*)(smem_raw + OFF_PS);
    int*   s_chg = (int*)(smem_raw + OFF_PS);     // reused during iterations

    const int b    = blockIdx.x;
    const int t    = threadIdx.x;
    const int w    = t >> 5;        // warp 0..15
    const int lane = t & 31;
    const int lq   = lane >> 2;     // 0..7
    const int lr   = lane & 3;      // 0..3
    const float* __restrict__ Cb = C + (size_t)b * 65536;

    // ---------- Build K = exp(-C/eps) (bf16, padded rows), deep MLP ----------
    #pragma unroll 8
    for (int k = 0; k < 32; k++) {
        int idx4 = k * 512 + t;
        float4 c = ((const float4*)Cb)[idx4];
        int lin = idx4 << 2;
        int n = lin >> 8;
        int m = lin & 255;
        __nv_bfloat162 p0 = __floats2bfloat162_rn(__expf(-c.x * INV_EPS),
                                                  __expf(-c.y * INV_EPS));
        __nv_bfloat162 p1 = __floats2bfloat162_rn(__expf(-c.z * INV_EPS),
                                                  __expf(-c.w * INV_EPS));
        *(__nv_bfloat162*)&sK[n * KROW_H + m]     = p0;
        *(__nv_bfloat162*)&sK[n * KROW_H + m + 2] = p1;
    }

    // ---------- Normalize masses (threads 0-255), s_ps scratch ----------
    if (t < 256) {
        float mpv = mass_pred[b * 256 + t];
        float mtv = mass_target[b * 256 + t];
        float sa = mpv, sb = mtv;
        #pragma unroll
        for (int o = 16; o; o >>= 1) {
            sa += __shfl_xor_sync(0xffffffffu, sa, o);
            sb += __shfl_xor_sync(0xffffffffu, sb, o);
        }
        if ((t & 31) == 0) { s_ps[t >> 5] = sa; s_ps[8 + (t >> 5)] = sb; }
        s_ps[64 + t]  = mpv;
        s_ps[320 + t] = mtv;
    }
    // init uperm = all 1.0 bf16 pairs
    if (t < 160) uperm[t] = 0x3F803F80u;
    __syncthreads();
    if (t < 256) {
        float suma = 0.f, sumb = 0.f;
        #pragma unroll
        for (int q = 0; q < 8; q++) { suma += s_ps[q]; sumb += s_ps[8 + q]; }
        s_a[t] = s_ps[64 + t]  / (suma + EPS_DIV);
        s_b[t] = s_ps[320 + t] / (sumb + EPS_DIV);
        s_u[t] = 1.0f;
    }
    __syncthreads();

    // ---------- Persistent A-frags of K^T: warp's 16 cols x all 256 rows ----------
    uint32_t af[16][4];
    #pragma unroll
    for (int kt = 0; kt < 16; kt++) {
        int r = 16*kt + 2*lr;
        int c = 16*w + lq;
        af[kt][0] = ld2k(sK, r,     c);
        af[kt][1] = ld2k(sK, r,     c + 8);
        af[kt][2] = ld2k(sK, r + 8, c);
        af[kt][3] = ld2k(sK, r + 8, c + 8);
    }

    // Hoisted per-thread constants
    const float sa0 = s_a[16*w + lq];
    const float sa1 = s_a[16*w + lq + 8];
    const float sb0 = s_b[16*w + lq];
    const float sb1 = s_b[16*w + lq + 8];
    const int rA = (16*w + lq)     * ROWW_W;
    const int rB = (16*w + lq + 8) * ROWW_W;

    uint32_t pu = 0u;        // previous bf16x2 image of (u0,u1); 0 != any image

    // ---------- Sinkhorn iterations with exact-fixed-point exit ----------
    for (int it = 0; it < ITERS; it++) {
        // ===== matvec1: Kt_u for cols 16w..+15 (af as A, u-perm as B) =====
        {
            float d0[4] = {0,0,0,0}, d1[4] = {0,0,0,0};
            float d2[4] = {0,0,0,0}, d3[4] = {0,0,0,0};
            #pragma unroll
            for (int s = 0; s < 8; s++) {
                uint4 bb = up4[9*lr + s];          // (b0,b1) for kt=2s and 2s+1
                int k0 = 2*s, k1 = 2*s + 1;
                int s0 = k0 & 3, s1 = k1 & 3;
                mma16816(d0[s0], d1[s0], d2[s0], d3[s0],
                         af[k0][0], af[k0][1], af[k0][2], af[k0][3], bb.x, bb.y);
                mma16816(d0[s1], d1[s1], d2[s1], d3[s1],
                         af[k1][0], af[k1][1], af[k1][2], af[k1][3], bb.z, bb.w);
            }
            float ktu0 = (d0[0] + d0[1]) + (d0[2] + d0[3]);
            float ktu1 = (d2[0] + d2[1]) + (d2[2] + d2[3]);
            float v0 = __fdividef(sb0, ktu0 + EPS_DIV);
            float v1 = __fdividef(sb1, ktu1 + EPS_DIV);
            if (lr == 0) { s_v[16*w + lq] = v0; s_v[16*w + lq + 8] = v1; }
            publish_perm(vperm, w, lane, v0, v1);
        }
        __syncthreads();

        // ===== matvec2: K_v for rows 16w..+15 (smem K as A, v-perm as B) =====
        {
            float d0[4] = {0,0,0,0}, d1[4] = {0,0,0,0};
            float d2[4] = {0,0,0,0}, d3[4] = {0,0,0,0};
            #pragma unroll
            for (int s = 0; s < 8; s++) {
                uint4 bb = vp4[9*lr + s];
                #pragma unroll
                for (int q = 0; q < 2; q++) {
                    int kt = 2*s + q;
                    int ss = kt & 3;
                    uint32_t a0 = sKw[rA + 8*kt + lr];
                    uint32_t a1 = sKw[rB + 8*kt + lr];
                    uint32_t a2 = sKw[rA + 8*kt + lr + 4];
                    uint32_t a3 = sKw[rB + 8*kt + lr + 4];
                    mma16816(d0[ss], d1[ss], d2[ss], d3[ss],
                             a0, a1, a2, a3,
                             q ? bb.z : bb.x, q ? bb.w : bb.y);
                }
            }
            float kv0 = (d0[0] + d0[1]) + (d0[2] + d0[3]);
            float kv1 = (d2[0] + d2[1]) + (d2[2] + d2[3]);
            float u0 = __fdividef(sa0, kv0 + EPS_DIV);
            float u1 = __fdividef(sa1, kv1 + EPS_DIV);
            if (lr == 0) { s_u[16*w + lq] = u0; s_u[16*w + lq + 8] = u1; }
            publish_perm(uperm, w, lane, u0, u1);

            // -- convergence flag: has the bf16 image of u changed? --
            __nv_bfloat162 upk = __floats2bfloat162_rn(u0, u1);
            uint32_t uw = *(uint32_t*)&upk;
            int ch = __any_sync(0xffffffffu, uw != pu);
            pu = uw;
            if (lane == 0) s_chg[w] = ch;
        }
        __syncthreads();

        // CTA-uniform exit (bf16 image stable => all later iters no-op)
        {
            int4 c0 = *(const int4*)&s_chg[0];
            int4 c1 = *(const int4*)&s_chg[4];
            int4 c2 = *(const int4*)&s_chg[8];
            int4 c3 = *(const int4*)&s_chg[12];
            int any = (c0.x | c0.y | c0.z | c0.w) | (c1.x | c1.y | c1.z | c1.w)
                    | (c2.x | c2.y | c2.z | c2.w) | (c3.x | c3.y | c3.z | c3.w);
            if (!any) break;
        }
    }
    __syncthreads();

    // ---------- ot_cost[b] = sum u[n] K[n,m] v[m] C[n,m] (C from L2) ----------
    float accf = 0.f;
    #pragma unroll 4
    for (int k = 0; k < 32; k++) {
        int idx4 = k * 512 + t;
        float4 c = ((const float4*)Cb)[idx4];
        int lin = idx4 << 2;
        int n = lin >> 8;
        int m = lin & 255;
        uint2 q = *(const uint2*)&sKw[n * ROWW_W + (m >> 1)];
        float un = s_u[n];
        float4 vv = *(const float4*)&s_v[m];
        accf += un * (bflo(q.x) * vv.x * c.x + bfhi(q.x) * vv.y * c.y
                    + bflo(q.y) * vv.z * c.z + bfhi(q.y) * vv.w * c.w);
    }
    #pragma unroll
    for (int o = 16; o; o >>= 1) accf += __shfl_xor_sync(0xffffffffu, accf, o);
    __syncthreads();
    if ((t & 31) == 0) s_ps[t >> 5] = accf;
    __syncthreads();

    __shared__ int s_last;
    if (t == 0) {
        float s = 0.f;
        #pragma unroll
        for (int q = 0; q < 16; q++) s += s_ps[q];
        g_cost[b] = s;
        __threadfence();
        unsigned int done = atomicAdd(&g_done, 1u);
        s_last = (done == B_TOT - 1);
    }
    __syncthreads();

    // ---------- Last CTA: deterministic fixed-tree mean over g_cost ----------
    if (s_last) {
        __threadfence();                 // acquire: all g_cost writes visible
        float s = g_cost[t] + g_cost[t + 512];
        #pragma unroll
        for (int o = 16; o; o >>= 1) s += __shfl_xor_sync(0xffffffffu, s, o);
        if (lane == 0) s_ps[w] = s;
        __syncthreads();
        if (t == 0) {
            float tot = 0.f;
            #pragma unroll
            for (int q = 0; q < 16; q++) tot += s_ps[q];
            out[0] = tot * (1.0f / B_TOT);
            g_done = 0;                  // self-reset for graph replay
        }
    }
}

extern "C" void kernel_launch(void* const* d_in, const int* in_sizes, int n_in,
                              void* d_out, int out_size)
{
    const float* C  = (const float*)d_in[0];
    const float* mp = (const float*)d_in[1];
    const float* mt = (const float*)d_in[2];
    float* out = (float*)d_out;

    cudaFuncSetAttribute(sinkhorn_kernel,
                         cudaFuncAttributeMaxDynamicSharedMemorySize, SMEM_BYTES);

    sinkhorn_kernel<<<B_TOT, 512, SMEM_BYTES>>>(C, mp, mt, out);
}